// round 14
// baseline (speedup 1.0000x reference)
#include <cuda_runtime.h>

// Problem shape (fixed by the dataset)
#define BATCH 8
#define CH    256
#define HH    128
#define WW    128
#define HO    64
#define WO    64
#define NPLANES 2048

// Dynamic smem layout. Paired log table, row-padded:
//   lp[129][66] of float2:  lp[r+1][j] = { log2(relu(col 2j-1)),
//                                          log2(relu(col 2j)) }   (input row r)
//   table row 0 (= input row -1) and col j=0 .x (= col -1) are -inf pads, so
//   out-of-range taps contribute ex2(-inf) = 0 with no predication.
//   sc[48] : [0..15] warp max partials, [32] invm, [33..41] w1 raw
#define LP_OFF 0
#define SC_OFF (129 * 66 * 2)
#define SMEM_FLOATS (SC_OFF + 48)
#define SMEM_BYTES  (SMEM_FLOATS * 4)

#define NINF __int_as_float(0xff800000)

__device__ __forceinline__ float f_lg2(float x) {
    float y; asm("lg2.approx.f32 %0, %1;" : "=f"(y) : "f"(x)); return y;
}
__device__ __forceinline__ float f_ex2(float x) {
    float y; asm("ex2.approx.f32 %0, %1;" : "=f"(y) : "f"(x)); return y;
}
__device__ __forceinline__ float f_rcp(float x) {
    float y; asm("rcp.approx.f32 %0, %1;" : "=f"(y) : "f"(x)); return y;
}

// One block = one (b,c) plane. 512 threads = (32, 16), 3 blocks/SM (42 regs).
// Phase 1: stream plane once, build padded paired-log table + plane max.
// Phase 2: thread (tx,ty) -> output PAIR wo=2tx,2tx+1, rows ho=4ty..4ty+3.
// Wide, aligned accesses: conv row = LDG.128+LDG.32; pool row = LDS.128+LDS.32;
// stores = STG.64. No carried rows (keeps live set under the 42-reg cap).
__global__ __launch_bounds__(512, 3) void fused_ppool_kernel(
    const float* __restrict__ bottom,
    const float* __restrict__ w1,
    const float* __restrict__ a1,
    const float* __restrict__ w2,
    const float* __restrict__ b2,
    float* __restrict__ out_res,
    float* __restrict__ out_p)
{
    extern __shared__ float smem[];
    float2* lp = (float2*)(smem + LP_OFF);
    float*  sc = smem + SC_OFF;

    const int plane = blockIdx.x;
    const int c = plane & (CH - 1);
    const float* __restrict__ src = bottom + (size_t)plane * (HH * WW);

    const int tx = threadIdx.x;          // 0..31 -> wo pair 2tx, 2tx+1
    const int ty = threadIdx.y;          // 0..15
    const int t  = ty * 32 + tx;         // 0..511
    const int wid = t >> 5, lid = t & 31;

    if (t < 9) sc[33 + t] = __ldg(&w1[c * 9 + t]);
    // -inf pads: table row 0 full pairs (j=0..64); col -1 (.x) for rows 1..128
    if (t < 65)              lp[t] = make_float2(NINF, NINF);
    if (t >= 65 && t < 193)  lp[(t - 64) * 66].x = NINF;

    // ---- Phase 1: stream plane (8192 float2), paired-log table + |x| max ----
    const float2* s2 = (const float2*)src;
    float mx = 0.f;
    #pragma unroll
    for (int i = 0; i < 16; i++) {
        int idx = t + i * 512;           // float2 idx: row = idx>>6, k = idx&63
        int r = idx >> 6, k = idx & 63;
        float2 v = __ldg(s2 + idx);
        lp[(r + 1) * 66 + k].y     = f_lg2(fmaxf(v.x, 0.f));  // col 2k
        lp[(r + 1) * 66 + k + 1].x = f_lg2(fmaxf(v.y, 0.f));  // col 2k+1
        mx = fmaxf(mx, fmaxf(fabsf(v.x), fabsf(v.y)));
    }
    #pragma unroll
    for (int o = 16; o; o >>= 1) mx = fmaxf(mx, __shfl_xor_sync(0xffffffffu, mx, o));
    if (lid == 0) sc[wid] = mx;
    __syncthreads();
    if (t < 16) {
        float m = sc[t];
        #pragma unroll
        for (int o = 8; o; o >>= 1) m = fmaxf(m, __shfl_xor_sync(0xffffu, m, o));
        if (t == 0) sc[32] = 1.0f / (m + 1.0f);
    }
    __syncthreads();

    // Fold 1/m into the conv weights (conv(x/m) = conv_{w/m}(x)).
    const float invm = sc[32];
    float w[9];
    #pragma unroll
    for (int i = 0; i < 9; i++) w[i] = sc[33 + i] * invm;
    const float av = __ldg(&a1[c]);
    const float wv = __ldg(&w2[c]);
    const float bv = __ldg(&b2[c]);

    // ---- Phase 2: 4 output pairs per thread ----
    #pragma unroll
    for (int g = 0; g < 4; g++) {
        const int ho = 4 * ty + g;
        const int rbase = 2 * ho - 1;        // top tap row (-1 only when ho=0)

        // Conv: both windows span cols 4tx-1 .. 4tx+3 over 3 rows.
        float c0 = 0.f, c1 = 0.f;
        {
            const float* srow = src + rbase * WW + 4 * tx;
            #pragma unroll
            for (int ki = 0; ki < 3; ki++) {
                const bool rv = (rbase + ki) >= 0;
                float  vm = (rv && tx > 0) ? __ldg(srow - 1) : 0.f;
                float4 q  = rv ? __ldg((const float4*)srow)
                               : make_float4(0.f, 0.f, 0.f, 0.f);
                const float wa = w[ki * 3], wb = w[ki * 3 + 1], wc = w[ki * 3 + 2];
                c0 = fmaf(wa, vm,  fmaf(wb, q.x, fmaf(wc, q.y, c0)));
                c1 = fmaf(wa, q.y, fmaf(wb, q.z, fmaf(wc, q.w, c1)));
                srow += WW;
            }
        }

        // PReLU + affine + clamp -> exponents
        float x0 = c0 > 0.f ? c0 : av * c0;
        float p0 = fminf(fmaxf(fmaf(x0, wv, bv), 1.0f), 110.0f);
        float x1 = c1 > 0.f ? c1 : av * c1;
        float p1 = fminf(fmaxf(fmaf(x1, wv, bv), 1.0f), 110.0f);

        // Pooling: table rows 2ho..2ho+2; per row one aligned LDS.128
        // ({lp[2tx], lp[2tx+1]}) + one LDS.32 (lp[2tx+2].x).
        //   wo=2tx  : taps q.x (col 4tx-1), q.y (4tx), q.z (4tx+1)
        //   wo=2tx+1: taps q.z (4tx+1), q.w (4tx+2), e (4tx+3)
        float s0 = 0.f, s1 = 0.f;
        {
            const float2* lrow = lp + (2 * ho) * 66 + 2 * tx;
            #pragma unroll
            for (int ki = 0; ki < 3; ki++) {
                float4 q = *(const float4*)lrow;
                float  e = lrow[2].x;
                s0 += f_ex2(p0 * q.x) + f_ex2(p0 * q.y) + f_ex2(p0 * q.z);
                s1 += f_ex2(p1 * q.z) + f_ex2(p1 * q.w) + f_ex2(p1 * e);
                lrow += 66;
            }
        }

        float m0 = fmaf(s0, (1.0f / 9.0f), 1e-12f);
        float m1 = fmaf(s1, (1.0f / 9.0f), 1e-12f);
        float r0 = f_ex2(f_lg2(m0) * f_rcp(p0));
        float r1 = f_ex2(f_lg2(m1) * f_rcp(p1));

        const size_t o = ((size_t)plane * HO + ho) * WO + 2 * tx;
        *(float2*)(out_res + o) = make_float2(r0, r1);
        *(float2*)(out_p   + o) = make_float2(p0, p1);
    }
}

extern "C" void kernel_launch(void* const* d_in, const int* in_sizes, int n_in,
                              void* d_out, int out_size) {
    const float* bottom = (const float*)d_in[0];
    const float* w1     = (const float*)d_in[1];
    const float* a1     = (const float*)d_in[2];
    const float* w2     = (const float*)d_in[3];
    const float* b2     = (const float*)d_in[4];
    float* out = (float*)d_out;
    const size_t N = (size_t)BATCH * CH * HO * WO;   // elements per output tensor

    cudaFuncSetAttribute(fused_ppool_kernel,
                         cudaFuncAttributeMaxDynamicSharedMemorySize, SMEM_BYTES);

    dim3 blk(32, 16);
    fused_ppool_kernel<<<NPLANES, blk, SMEM_BYTES>>>(bottom, w1, a1, w2, b2,
                                                     out, out + N);

    (void)in_sizes; (void)n_in; (void)out_size;
}

// round 15
// speedup vs baseline: 1.0618x; 1.0618x over previous
#include <cuda_runtime.h>

// Problem shape (fixed by the dataset)
#define BATCH 8
#define CH    256
#define HH    128
#define WW    128
#define HO    64
#define WO    64
#define NPLANES 2048

// Dynamic smem layout. Paired log table, row-padded:
//   lp[129][66] of float2:  lp[r+1][j] = { log2(relu(col 2j-1)),
//                                          log2(relu(col 2j)) }   (input row r)
//   table row 0 (= input row -1) and col j=0 .x (= col -1) are -inf pads, so
//   out-of-range taps contribute ex2(-inf) = 0 with no predication.
//   sc[56] : [0..15] warp max partials, [32] invm, [33..41] w1 raw,
//            [40..48] -> folded weights stored at [40+i] = w1[i]*invm
#define LP_OFF 0
#define SC_OFF (129 * 66 * 2)
#define SMEM_FLOATS (SC_OFF + 56)
#define SMEM_BYTES  (SMEM_FLOATS * 4)

#define NINF __int_as_float(0xff800000)

__device__ __forceinline__ float f_lg2(float x) {
    float y; asm("lg2.approx.f32 %0, %1;" : "=f"(y) : "f"(x)); return y;
}
__device__ __forceinline__ float f_ex2(float x) {
    float y; asm("ex2.approx.f32 %0, %1;" : "=f"(y) : "f"(x)); return y;
}
__device__ __forceinline__ float f_rcp(float x) {
    float y; asm("rcp.approx.f32 %0, %1;" : "=f"(y) : "f"(x)); return y;
}

// One block = one (b,c) plane. 512 threads = (64, 8), 3 blocks/SM (42 regs).
// Phase 1: stream plane once, build padded paired-log table + plane max.
// Phase 2: thread (tx,ty) -> wo=tx, ho=8ty..8ty+7 with carried-row reuse
// (top-row conv contribution carried as ONE pre-dotted scalar) and gmem rows
// software-pipelined one window ahead so LDG latency hides under the ex2 burst.
__global__ __launch_bounds__(512, 3) void fused_ppool_kernel(
    const float* __restrict__ bottom,
    const float* __restrict__ w1,
    const float* __restrict__ a1,
    const float* __restrict__ w2,
    const float* __restrict__ b2,
    float* __restrict__ out_res,
    float* __restrict__ out_p)
{
    extern __shared__ float smem[];
    float2* lp = (float2*)(smem + LP_OFF);
    float*  sc = smem + SC_OFF;

    const int plane = blockIdx.x;
    const int c = plane & (CH - 1);
    const float* __restrict__ src = bottom + (size_t)plane * (HH * WW);

    const int tx = threadIdx.x;          // 0..63 -> wo
    const int ty = threadIdx.y;          // 0..7
    const int t  = ty * 64 + tx;         // 0..511
    const int wid = t >> 5, lid = t & 31;

    if (t < 9) sc[33 + t] = __ldg(&w1[c * 9 + t]);
    // -inf pads: table row 0 full pairs (j=0..64); col -1 (.x) for rows 1..128
    if (t < 65)              lp[t] = make_float2(NINF, NINF);
    if (t >= 65 && t < 193)  lp[(t - 64) * 66].x = NINF;

    // ---- Phase 1: stream plane (8192 float2), paired-log table + |x| max ----
    const float2* s2 = (const float2*)src;
    float mx = 0.f;
    #pragma unroll
    for (int i = 0; i < 16; i++) {
        int idx = t + i * 512;           // float2 idx: row = idx>>6, k = idx&63
        int r = idx >> 6, k = idx & 63;
        float2 v = __ldg(s2 + idx);
        lp[(r + 1) * 66 + k].y     = f_lg2(fmaxf(v.x, 0.f));  // col 2k
        lp[(r + 1) * 66 + k + 1].x = f_lg2(fmaxf(v.y, 0.f));  // col 2k+1
        mx = fmaxf(mx, fmaxf(fabsf(v.x), fabsf(v.y)));
    }
    #pragma unroll
    for (int o = 16; o; o >>= 1) mx = fmaxf(mx, __shfl_xor_sync(0xffffffffu, mx, o));
    if (lid == 0) sc[wid] = mx;
    __syncthreads();
    if (t < 16) {
        float m = sc[t];
        #pragma unroll
        for (int o = 8; o; o >>= 1) m = fmaxf(m, __shfl_xor_sync(0xffffu, m, o));
        if (t == 0) sc[32] = 1.0f / (m + 1.0f);
    }
    __syncthreads();
    // Fold 1/m into the conv weights, kept in SMEM so ptxas can reload rather
    // than spill under the 42-reg cap. (conv(x/m) = conv_{w/m}(x).)
    if (t < 9) sc[40 + t] = sc[33 + t] * sc[32];
    __syncthreads();

    const float av = __ldg(&a1[c]);
    const float wv = __ldg(&w2[c]);
    const float bv = __ldg(&b2[c]);

    // ---- Phase 2: 8 vertically-adjacent outputs, pipelined ----
    const int ho0 = ty * 8;

    // Carried top row contribution (input row 2*ho0-1), pre-dotted with w0..w2.
    float atop;
    float la0, la1, la2;
    {
        const float* srowt = src + (2 * ho0 - 1) * WW + 2 * tx;
        bool rv = (ho0 > 0);
        float am = (rv && tx > 0) ? __ldg(srowt - 1) : 0.f;
        float2 q = rv ? __ldg((const float2*)srowt) : make_float2(0.f, 0.f);
        atop = sc[40] * am;
        atop = fmaf(sc[41], q.x, atop);
        atop = fmaf(sc[42], q.y, atop);
        float2 lq = lp[2 * ho0 * 66 + tx];
        la0 = lq.x; la1 = lq.y;
        la2 = lp[2 * ho0 * 66 + tx + 1].x;
    }

    const float*  srow = src + (2 * ho0) * WW + 2 * tx;   // mid row of 1st win
    const float2* lrow = lp + (2 * ho0 + 1) * 66 + tx;
    size_t o = ((size_t)plane * HO + ho0) * WO + tx;

    // Preload window 0's mid (2ho0) and bottom (2ho0+1) raw rows.
    float  bm = (tx > 0) ? __ldg(srow - 1) : 0.f;
    float2 bq = __ldg((const float2*)srow);
    float  cm = (tx > 0) ? __ldg(srow + WW - 1) : 0.f;
    float2 cq = __ldg((const float2*)(srow + WW));

    #pragma unroll
    for (int g = 0; g < 8; g++) {
        // Prefetch next window's raw rows (rows 2ho+2, 2ho+3); the LDGs retire
        // while this iteration's MUFU burst executes. g<7 is compile-time.
        float nbm = 0.f, ncm = 0.f;
        float2 nbq = make_float2(0.f, 0.f), ncq = make_float2(0.f, 0.f);
        if (g < 7) {
            const float* nr = srow + 2 * WW;
            nbm = (tx > 0) ? __ldg(nr - 1) : 0.f;
            nbq = __ldg((const float2*)nr);
            ncm = (tx > 0) ? __ldg(nr + WW - 1) : 0.f;
            ncq = __ldg((const float2*)(nr + WW));
        }

        // Log taps for this window (table rows 2ho+1, 2ho+2).
        float2 lbq = lrow[0];
        float  lb2 = lrow[1].x;
        float2 lcq = lrow[66];
        float  lc2 = lrow[67].x;

        // Depthwise conv: carried top dot + mid/bottom rows (smem weights).
        float conv = atop;
        conv = fmaf(sc[43], bm,   conv);
        conv = fmaf(sc[44], bq.x, conv);
        conv = fmaf(sc[45], bq.y, conv);
        conv = fmaf(sc[46], cm,   conv);
        conv = fmaf(sc[47], cq.x, conv);
        conv = fmaf(sc[48], cq.y, conv);

        // Pre-dot next window's top row (= this bottom row) with w0..w2.
        atop = sc[40] * cm;
        atop = fmaf(sc[41], cq.x, atop);
        atop = fmaf(sc[42], cq.y, atop);

        // PReLU + affine + clamp -> exponent p
        float x = conv > 0.f ? conv : av * conv;
        float p = fminf(fmaxf(fmaf(x, wv, bv), 1.0f), 110.0f);

        // Power-mean over the 3x3 window
        float sum = f_ex2(p * la0)   + f_ex2(p * la1)   + f_ex2(p * la2)
                  + f_ex2(p * lbq.x) + f_ex2(p * lbq.y) + f_ex2(p * lb2)
                  + f_ex2(p * lcq.x) + f_ex2(p * lcq.y) + f_ex2(p * lc2);

        float mean = fmaf(sum, (1.0f / 9.0f), 1e-12f);
        float res  = f_ex2(f_lg2(mean) * f_rcp(p));

        out_res[o] = res;
        out_p[o]   = p;

        // Shift pipeline: bottom logs become next top logs; prefetched rows
        // become current rows.
        la0 = lcq.x; la1 = lcq.y; la2 = lc2;
        bm = nbm; bq = nbq; cm = ncm; cq = ncq;
        srow += 2 * WW;
        lrow += 2 * 66;
        o += WO;
    }
}

extern "C" void kernel_launch(void* const* d_in, const int* in_sizes, int n_in,
                              void* d_out, int out_size) {
    const float* bottom = (const float*)d_in[0];
    const float* w1     = (const float*)d_in[1];
    const float* a1     = (const float*)d_in[2];
    const float* w2     = (const float*)d_in[3];
    const float* b2     = (const float*)d_in[4];
    float* out = (float*)d_out;
    const size_t N = (size_t)BATCH * CH * HO * WO;   // elements per output tensor

    cudaFuncSetAttribute(fused_ppool_kernel,
                         cudaFuncAttributeMaxDynamicSharedMemorySize, SMEM_BYTES);

    dim3 blk(64, 8);
    fused_ppool_kernel<<<NPLANES, blk, SMEM_BYTES>>>(bottom, w1, a1, w2, b2,
                                                     out, out + N);

    (void)in_sizes; (void)n_in; (void)out_size;
}